// round 17
// baseline (speedup 1.0000x reference)
#include <cuda_runtime.h>
#include <cuda_fp16.h>
#include <cstdint>

// PatternDetector: B=131072 rows x L=256 int32 in [0,40). Output Bx4 f32.
//
// Stable "nonzeros-first" argsort preserves order -> all features are
// functions of consecutive-nonzero pairs -> forward scan per row.
// dec = (n-1) - rep - inc.
//
// R17 = R10 (persistent, TPB=64, 16-row tiles, double buffer, repack to
// 80B-slot packed bytes, SWAR half2 scan) with the per-thread cp.async
// loop replaced by ONE cp.async.bulk (UBLKCP) of 16KB per tile, completion
// via mbarrier complete_tx. Tests whether the 5.3 TB/s plateau is caused
// by 16B-granular request streams vs the bulk async-copy path.

constexpr int TPB        = 64;     // threads = chunks per tile
constexpr int ROWS_TILE  = 16;
constexpr int L_LEN      = 256;
constexpr int TILE_BYTES = ROWS_TILE * L_LEN * 4;   // 16384
constexpr int TILE_INT4  = TILE_BYTES / 16;         // 1024
constexpr int CSTRIDE    = 80;     // 64B chunk in 20-word slot (conflict-free)
constexpr int GRID       = 888;    // 148 SM x 6 blocks

__device__ __forceinline__ unsigned heq2_mask(unsigned a, unsigned b) {
    unsigned d; asm("set.eq.u32.f16x2 %0, %1, %2;" : "=r"(d) : "r"(a), "r"(b)); return d;
}
__device__ __forceinline__ unsigned hgt2_mask(unsigned a, unsigned b) {
    unsigned d; asm("set.gt.u32.f16x2 %0, %1, %2;" : "=r"(d) : "r"(a), "r"(b)); return d;
}
__device__ __forceinline__ unsigned hne2_mask(unsigned a, unsigned b) {
    unsigned d; asm("set.ne.u32.f16x2 %0, %1, %2;" : "=r"(d) : "r"(a), "r"(b)); return d;
}

__device__ __forceinline__ void last2nz_word(unsigned w, int& p1, int& p2, int& cnt)
{
    p1 = 0; p2 = 0; cnt = 0;
    #pragma unroll
    for (int k = 0; k < 4; ++k) {
        int v = (w >> (8 * k)) & 0xff;
        bool nz = (v != 0);
        p2 = nz ? p1 : p2;
        p1 = nz ? v  : p1;
        cnt += nz;
    }
}

__device__ __forceinline__ void mbar_wait(unsigned mbar_addr, int parity)
{
    asm volatile(
        "{\n\t"
        ".reg .pred P;\n\t"
        "WAIT_%=:\n\t"
        "mbarrier.try_wait.parity.acquire.cta.shared::cta.b64 P, [%0], %1, 0x989680;\n\t"
        "@P bra.uni DONE_%=;\n\t"
        "bra.uni WAIT_%=;\n\t"
        "DONE_%=:\n\t"
        "}"
        :: "r"(mbar_addr), "r"(parity) : "memory");
}

__global__ void __launch_bounds__(TPB, 6) pattern_kernel(
    const int4* __restrict__ x4, float4* __restrict__ out, int total_tiles)
{
    __shared__ alignas(128) unsigned char raw[2][TILE_BYTES];   // 32768
    __shared__ unsigned char packed[TPB * CSTRIDE];             // 5120
    __shared__ alignas(8) unsigned long long mbar[2];

    const int tid = threadIdx.x;
    const unsigned mbar_u = (unsigned)__cvta_generic_to_shared(&mbar[0]);
    const unsigned raw_u  = (unsigned)__cvta_generic_to_shared(&raw[0][0]);

    if (tid == 0) {
        asm volatile("mbarrier.init.shared.b64 [%0], 1;" :: "r"(mbar_u)     : "memory");
        asm volatile("mbarrier.init.shared.b64 [%0], 1;" :: "r"(mbar_u + 8) : "memory");
    }
    __syncthreads();

    int t = blockIdx.x;
    if (tid == 0 && t < total_tiles) {
        asm volatile("mbarrier.arrive.expect_tx.shared.b64 _, [%0], %1;"
                     :: "r"(mbar_u), "r"((unsigned)TILE_BYTES) : "memory");
        asm volatile("cp.async.bulk.shared::cta.global.mbarrier::complete_tx::bytes "
                     "[%0], [%1], %2, [%3];"
                     :: "r"(raw_u),
                        "l"((const char*)x4 + (long long)t * TILE_BYTES),
                        "r"((unsigned)TILE_BYTES), "r"(mbar_u) : "memory");
    }

    const int c         = tid & 3;      // chunk within row
    const int row_chunk = tid & ~3;
    int ph0 = 0, ph1 = 0;
    int buf = 0;

    for (; t < total_tiles; t += GRID, buf ^= 1) {
        // ---- wait current buffer's bulk copy (acquire) ----
        mbar_wait(mbar_u + buf * 8, buf ? ph1 : ph0);
        if (buf) ph1 ^= 1; else ph0 ^= 1;

        // everyone past the wait; also proves packed-scan of prev iter done
        __syncthreads();

        // ---- overlap: issue next tile into the other buffer ----
        int tn = t + GRID;
        if (tid == 0 && tn < total_tiles) {
            unsigned mb = mbar_u + (buf ^ 1) * 8;
            asm volatile("mbarrier.arrive.expect_tx.shared.b64 _, [%0], %1;"
                         :: "r"(mb), "r"((unsigned)TILE_BYTES) : "memory");
            asm volatile("cp.async.bulk.shared::cta.global.mbarrier::complete_tx::bytes "
                         "[%0], [%1], %2, [%3];"
                         :: "r"(raw_u + (buf ^ 1) * TILE_BYTES),
                            "l"((const char*)x4 + (long long)tn * TILE_BYTES),
                            "r"((unsigned)TILE_BYTES), "r"(mb) : "memory");
        }

        // ---- repack: linear raw int32 -> packed bytes (conflict-free) ----
        const int4* rp = (const int4*)&raw[buf][0];
        #pragma unroll
        for (int i = 0; i < TILE_INT4 / TPB; ++i) {
            int idx = i * TPB + tid;
            int4 v  = rp[idx];
            unsigned lo = __byte_perm((unsigned)v.x, (unsigned)v.y, 0x0040);
            unsigned hi = __byte_perm((unsigned)v.z, (unsigned)v.w, 0x0040);
            unsigned pk = __byte_perm(lo, hi, 0x5410);
            *(unsigned*)&packed[(idx >> 4) * CSTRIDE + (idx & 15) * 4] = pk;
        }
        __syncthreads();

        // ---- chain inits (peek in packed buffer) ----
        int a1 = 127, a2 = 127;
        if (c) {
            unsigned w = *(const unsigned*)&packed[(tid - 1) * CSTRIDE + 60];
            int p1, p2, cnt;
            last2nz_word(w, p1, p2, cnt);
            if (cnt >= 2) { a1 = p1; a2 = p2; }
            else {
                int j = c * 64 - 1, found = 0;
                while (j >= 0 && found < 2) {
                    int v = packed[(row_chunk + (j >> 6)) * CSTRIDE + (j & 63)];
                    if (v) { if (!found) a1 = v; else a2 = v; ++found; }
                    --j;
                }
            }
        }
        int b1 = 127, b2 = 127;
        {
            // word holding elements 28..31 of THIS chunk = byte offset 28
            unsigned w = *(const unsigned*)&packed[tid * CSTRIDE + 28];
            int p1, p2, cnt;
            last2nz_word(w, p1, p2, cnt);
            if (cnt >= 2) { b1 = p1; b2 = p2; }
            else {
                int j = c * 64 + 31, found = 0;
                while (j >= 0 && found < 2) {
                    int v = packed[(row_chunk + (j >> 6)) * CSTRIDE + (j & 63)];
                    if (v) { if (!found) b1 = v; else b2 = v; ++found; }
                    --j;
                }
            }
        }

        // ---- SWAR scan: low half = chain A (0-31), high = B (32-63) ----
        const unsigned BIAS = 0x64006400u;
        const unsigned BMSK = 0x00FF00FFu;
        unsigned p1h = (unsigned)(0x6400 | a1) | ((unsigned)(0x6400 | b1) << 16);
        unsigned p2h = (unsigned)(0x6400 | a2) | ((unsigned)(0x6400 | b2) << 16);
        unsigned accR = 0, accI = 0, accP = 0, accN = 0;

        const uint4* chunk = (const uint4*)&packed[tid * CSTRIDE];
        #pragma unroll
        for (int h = 0; h < 2; ++h) {
            uint4 qa = chunk[h];        // A words: elems h*16 .. h*16+15
            uint4 qb = chunk[2 + h];    // B words: elems 32+h*16 ..
            unsigned WAh[4] = {qa.x, qa.y, qa.z, qa.w};
            unsigned WBh[4] = {qb.x, qb.y, qb.z, qb.w};
            #pragma unroll
            for (int w = 0; w < 4; ++w) {
                unsigned wa = WAh[w], wb = WBh[w];
                #pragma unroll
                for (int k = 0; k < 4; ++k) {
                    unsigned pr = __byte_perm(wa, wb, 0x0400 + k * 0x0101);
                    unsigned v  = (pr & BMSK) | BIAS;
                    unsigned mR = heq2_mask(v, p1h);
                    unsigned mI = hgt2_mask(v, p1h);
                    unsigned mP = heq2_mask(v, p2h);
                    unsigned mN = hne2_mask(v, BIAS);
                    accR = __vsub2(accR, mR);
                    accI = __vsub2(accI, mI);
                    accP = __vsub2(accP, mP);
                    accN = __vsub2(accN, mN);
                    p2h = (p1h & mN) | (p2h & ~mN);
                    p1h = (v   & mN) | (p1h & ~mN);
                }
            }
        }

        // ---- reduce the 4 chunk lanes (u16 sums <= 256, no overflow) ----
        #pragma unroll
        for (int m = 1; m <= 2; m <<= 1) {
            accR = __vadd2(accR, __shfl_xor_sync(0xffffffffu, accR, m));
            accI = __vadd2(accI, __shfl_xor_sync(0xffffffffu, accI, m));
            accP = __vadd2(accP, __shfl_xor_sync(0xffffffffu, accP, m));
            accN = __vadd2(accN, __shfl_xor_sync(0xffffffffu, accN, m));
        }

        if (c == 0) {
            int REP = (int)(accR & 0xffffu) + (int)(accR >> 16);
            int INC = (int)(accI & 0xffffu) + (int)(accI >> 16);
            int PER = (int)(accP & 0xffffu) + (int)(accP >> 16);
            int N   = (int)(accN & 0xffffu) + (int)(accN >> 16);
            float o0 = 0.f, o1 = 0.f, o2 = 0.f, o3 = 0.f;
            if (N > 1) {
                int DEC  = (N - 1) - REP - INC;
                float d1 = 1.0f / (float)(N - 1);
                o0 = (float)REP * d1;
                o1 = (float)INC * d1;
                o2 = (float)DEC * d1;
                if (N >= 4) o3 = (float)PER / (float)(N - 2);
            }
            out[(long long)t * ROWS_TILE + (tid >> 2)] =
                make_float4(o0, o1, o2, o3);
        }
    }
}

extern "C" void kernel_launch(void* const* d_in, const int* in_sizes, int n_in,
                              void* d_out, int out_size)
{
    const int4* x = (const int4*)d_in[0];
    float4* out   = (float4*)d_out;
    const int total_elems = in_sizes[0];              // B * L
    const int nrows       = total_elems / L_LEN;      // 131072
    const int total_tiles = nrows / ROWS_TILE;        // 8192
    const int grid = (total_tiles < GRID) ? total_tiles : GRID;
    pattern_kernel<<<grid, TPB>>>(x, out, total_tiles);
}